// round 10
// baseline (speedup 1.0000x reference)
#include <cuda_runtime.h>

// ComplexScaling: separable bilinear grid_sample, s = 1 + theta[0],
// align_corners=False, zeros padding. input [32,1024,1024,2] fp32 NHWC.
//
// Identity path (s == 1.0f is exact identity in fp32): warp-batched copy
// using sm_103a 256-bit global accesses (ld/st .v8.f32) -- 1KB contiguous
// per warp instruction, 2 chunks (64B) per thread (R8-best recipe),
// NT=512 for a shorter block-scheduling tail.
// Generic path: verified 4-corner bilinear, 4 pixels per 32B chunk.

#define HH 1024
#define WW 1024
#define NPIX (32 * HH * WW)      // total float2 pixels = 33,554,432
#define NCHUNK32 (NPIX / 4)      // 32B chunks = 8,388,608
#define NT 512
#define BATCH 2                  // 32B chunks per thread

struct v8 { float a0,a1,a2,a3,a4,a5,a6,a7; };

__device__ __forceinline__ v8 ldg_v8(const float* p)
{
    v8 v;
    asm volatile("ld.global.nc.v8.f32 {%0,%1,%2,%3,%4,%5,%6,%7}, [%8];"
                 : "=f"(v.a0), "=f"(v.a1), "=f"(v.a2), "=f"(v.a3),
                   "=f"(v.a4), "=f"(v.a5), "=f"(v.a6), "=f"(v.a7)
                 : "l"(p));
    return v;
}

__device__ __forceinline__ void stg_v8(float* p, const v8& v)
{
    asm volatile("st.global.v8.f32 [%0], {%1,%2,%3,%4,%5,%6,%7,%8};"
                 :: "l"(p),
                    "f"(v.a0), "f"(v.a1), "f"(v.a2), "f"(v.a3),
                    "f"(v.a4), "f"(v.a5), "f"(v.a6), "f"(v.a7)
                 : "memory");
}

__device__ __forceinline__ float4 bilinear_pair(const float2* __restrict__ img,
                                                int j0, float s,
                                                float mwy0, float mwy1,
                                                int cy0, int cy1)
{
    const int j1 = j0 + 1;
    const float xn0 = (2.0f * (float)j0 + 1.0f) * (1.0f / (float)WW) - 1.0f;
    const float xn1 = (2.0f * (float)j1 + 1.0f) * (1.0f / (float)WW) - 1.0f;
    const float ixa = ((s * xn0 + 1.0f) * (float)WW - 1.0f) * 0.5f;
    const float ixb = ((s * xn1 + 1.0f) * (float)WW - 1.0f) * 0.5f;
    const float fxa0 = floorf(ixa);
    const float fxb0 = floorf(ixb);
    const float wxa1 = ixa - fxa0;
    const float wxb1 = ixb - fxb0;
    const float wxa0 = 1.0f - wxa1;
    const float wxb0 = 1.0f - wxb1;
    const int xa0 = (int)fxa0;
    const int xb0 = (int)fxb0;
    const int xa1 = xa0 + 1;
    const int xb1 = xb0 + 1;

    const float mwxa0 = (xa0 >= 0 && xa0 < WW) ? wxa0 : 0.0f;
    const float mwxa1 = (xa1 >= 0 && xa1 < WW) ? wxa1 : 0.0f;
    const float mwxb0 = (xb0 >= 0 && xb0 < WW) ? wxb0 : 0.0f;
    const float mwxb1 = (xb1 >= 0 && xb1 < WW) ? wxb1 : 0.0f;
    const int cxa0 = min(max(xa0, 0), WW - 1);
    const int cxa1 = min(max(xa1, 0), WW - 1);
    const int cxb0 = min(max(xb0, 0), WW - 1);
    const int cxb1 = min(max(xb1, 0), WW - 1);

    const float2* r0 = img + (size_t)cy0 * WW;
    const float2* r1 = img + (size_t)cy1 * WW;

    const float2 a00 = __ldg(r0 + cxa0);
    const float2 a01 = __ldg(r0 + cxa1);
    const float2 a10 = __ldg(r1 + cxa0);
    const float2 a11 = __ldg(r1 + cxa1);
    const float2 b00 = __ldg(r0 + cxb0);
    const float2 b01 = __ldg(r0 + cxb1);
    const float2 b10 = __ldg(r1 + cxb0);
    const float2 b11 = __ldg(r1 + cxb1);

    float4 res;
    {
        const float r0x = mwxa0 * a00.x + mwxa1 * a01.x;
        const float r0y = mwxa0 * a00.y + mwxa1 * a01.y;
        const float r1x = mwxa0 * a10.x + mwxa1 * a11.x;
        const float r1y = mwxa0 * a10.y + mwxa1 * a11.y;
        res.x = mwy0 * r0x + mwy1 * r1x;
        res.y = mwy0 * r0y + mwy1 * r1y;
    }
    {
        const float r0x = mwxb0 * b00.x + mwxb1 * b01.x;
        const float r0y = mwxb0 * b00.y + mwxb1 * b01.y;
        const float r1x = mwxb0 * b10.x + mwxb1 * b11.x;
        const float r1y = mwxb0 * b10.y + mwxb1 * b11.y;
        res.z = mwy0 * r0x + mwy1 * r1x;
        res.w = mwy0 * r0y + mwy1 * r1y;
    }
    return res;
}

__global__ __launch_bounds__(NT)
void complex_scaling_kernel(const float2* __restrict__ in,
                            const float* __restrict__ theta,
                            float2* __restrict__ out)
{
    const float s = 1.0f + __ldg(theta);
    const size_t base = (size_t)blockIdx.x * (NT * BATCH) + threadIdx.x;

    if (s == 1.0f) {
        // ---- identity: 256-bit warp-batched copy (1KB per warp instr) ----
        const float* src = reinterpret_cast<const float*>(in) + base * 8;
        float* dst       = reinterpret_cast<float*>(out) + base * 8;
        const v8 v0 = ldg_v8(src + 0 * NT * 8);
        const v8 v1 = ldg_v8(src + 1 * NT * 8);
        stg_v8(dst + 0 * NT * 8, v0);
        stg_v8(dst + 1 * NT * 8, v1);
        return;
    }

    // ---- generic bilinear path: BATCH 32B chunks, 4 pixels each ----
    #pragma unroll
    for (int k = 0; k < BATCH; k++) {
        const size_t c = base + (size_t)k * NT;   // 32B chunk index
        const int p   = (int)(c * 4);             // first pixel index
        const int n   = p >> 20;                  // / (HH*WW)
        const int rem = p & (HH * WW - 1);
        const int i   = rem >> 10;                // row
        const int j0  = rem & (WW - 1);           // first column (mult of 4)

        const float yn  = (2.0f * (float)i + 1.0f) * (1.0f / (float)HH) - 1.0f;
        const float iy  = ((s * yn + 1.0f) * (float)HH - 1.0f) * 0.5f;
        const float fy0 = floorf(iy);
        const float wy1 = iy - fy0;
        const float wy0 = 1.0f - wy1;
        const int y0 = (int)fy0;
        const int y1 = y0 + 1;
        const float mwy0 = (y0 >= 0 && y0 < HH) ? wy0 : 0.0f;
        const float mwy1 = (y1 >= 0 && y1 < HH) ? wy1 : 0.0f;
        const int cy0 = min(max(y0, 0), HH - 1);
        const int cy1 = min(max(y1, 0), HH - 1);

        const float2* img = in + (size_t)n * (HH * WW);
        float4* dst = reinterpret_cast<float4*>(out) + c * 2;
        dst[0] = bilinear_pair(img, j0,     s, mwy0, mwy1, cy0, cy1);
        dst[1] = bilinear_pair(img, j0 + 2, s, mwy0, mwy1, cy0, cy1);
    }
}

extern "C" void kernel_launch(void* const* d_in, const int* in_sizes, int n_in,
                              void* d_out, int out_size)
{
    const float2* in   = (const float2*)d_in[0];   // [32,1024,1024,2] fp32
    const float* theta = (const float*)d_in[1];    // [1] fp32
    float2* out        = (float2*)d_out;

    const int blocks = NCHUNK32 / (NT * BATCH);    // 8192
    complex_scaling_kernel<<<blocks, NT>>>(in, theta, out);
}

// round 11
// speedup vs baseline: 1.0082x; 1.0082x over previous
#include <cuda_runtime.h>

// ComplexScaling: separable bilinear grid_sample, s = 1 + theta[0],
// align_corners=False, zeros padding. input [32,1024,1024,2] fp32 NHWC.
//
// FINAL (R8-best recipe): identity path (s == 1.0f is exact identity in
// fp32 -- every intermediate op is a power-of-two scaling of small ints)
// does a warp-batched streaming copy with sm_103a 256-bit global accesses
// (ld/st .v8.f32): 1KB contiguous per warp instruction, 2 chunks (64B) per
// thread. Generic path: verified 4-corner bilinear, 4 pixels per 32B chunk.
// Measured: 82.05us total, DRAM 80%, ~6.34TB/s -- at the chip's mixed
// read/write stream ceiling with provably minimal traffic (512MB).

#define HH 1024
#define WW 1024
#define NPIX (32 * HH * WW)      // total float2 pixels = 33,554,432
#define NCHUNK32 (NPIX / 4)      // 32B chunks = 8,388,608
#define NT 256
#define BATCH 2                  // 32B chunks per thread

struct v8 { float a0,a1,a2,a3,a4,a5,a6,a7; };

__device__ __forceinline__ v8 ldg_v8(const float* p)
{
    v8 v;
    asm volatile("ld.global.nc.v8.f32 {%0,%1,%2,%3,%4,%5,%6,%7}, [%8];"
                 : "=f"(v.a0), "=f"(v.a1), "=f"(v.a2), "=f"(v.a3),
                   "=f"(v.a4), "=f"(v.a5), "=f"(v.a6), "=f"(v.a7)
                 : "l"(p));
    return v;
}

__device__ __forceinline__ void stg_v8(float* p, const v8& v)
{
    asm volatile("st.global.v8.f32 [%0], {%1,%2,%3,%4,%5,%6,%7,%8};"
                 :: "l"(p),
                    "f"(v.a0), "f"(v.a1), "f"(v.a2), "f"(v.a3),
                    "f"(v.a4), "f"(v.a5), "f"(v.a6), "f"(v.a7)
                 : "memory");
}

__device__ __forceinline__ float4 bilinear_pair(const float2* __restrict__ img,
                                                int j0, float s,
                                                float mwy0, float mwy1,
                                                int cy0, int cy1)
{
    const int j1 = j0 + 1;
    const float xn0 = (2.0f * (float)j0 + 1.0f) * (1.0f / (float)WW) - 1.0f;
    const float xn1 = (2.0f * (float)j1 + 1.0f) * (1.0f / (float)WW) - 1.0f;
    const float ixa = ((s * xn0 + 1.0f) * (float)WW - 1.0f) * 0.5f;
    const float ixb = ((s * xn1 + 1.0f) * (float)WW - 1.0f) * 0.5f;
    const float fxa0 = floorf(ixa);
    const float fxb0 = floorf(ixb);
    const float wxa1 = ixa - fxa0;
    const float wxb1 = ixb - fxb0;
    const float wxa0 = 1.0f - wxa1;
    const float wxb0 = 1.0f - wxb1;
    const int xa0 = (int)fxa0;
    const int xb0 = (int)fxb0;
    const int xa1 = xa0 + 1;
    const int xb1 = xb0 + 1;

    const float mwxa0 = (xa0 >= 0 && xa0 < WW) ? wxa0 : 0.0f;
    const float mwxa1 = (xa1 >= 0 && xa1 < WW) ? wxa1 : 0.0f;
    const float mwxb0 = (xb0 >= 0 && xb0 < WW) ? wxb0 : 0.0f;
    const float mwxb1 = (xb1 >= 0 && xb1 < WW) ? wxb1 : 0.0f;
    const int cxa0 = min(max(xa0, 0), WW - 1);
    const int cxa1 = min(max(xa1, 0), WW - 1);
    const int cxb0 = min(max(xb0, 0), WW - 1);
    const int cxb1 = min(max(xb1, 0), WW - 1);

    const float2* r0 = img + (size_t)cy0 * WW;
    const float2* r1 = img + (size_t)cy1 * WW;

    const float2 a00 = __ldg(r0 + cxa0);
    const float2 a01 = __ldg(r0 + cxa1);
    const float2 a10 = __ldg(r1 + cxa0);
    const float2 a11 = __ldg(r1 + cxa1);
    const float2 b00 = __ldg(r0 + cxb0);
    const float2 b01 = __ldg(r0 + cxb1);
    const float2 b10 = __ldg(r1 + cxb0);
    const float2 b11 = __ldg(r1 + cxb1);

    float4 res;
    {
        const float r0x = mwxa0 * a00.x + mwxa1 * a01.x;
        const float r0y = mwxa0 * a00.y + mwxa1 * a01.y;
        const float r1x = mwxa0 * a10.x + mwxa1 * a11.x;
        const float r1y = mwxa0 * a10.y + mwxa1 * a11.y;
        res.x = mwy0 * r0x + mwy1 * r1x;
        res.y = mwy0 * r0y + mwy1 * r1y;
    }
    {
        const float r0x = mwxb0 * b00.x + mwxb1 * b01.x;
        const float r0y = mwxb0 * b00.y + mwxb1 * b01.y;
        const float r1x = mwxb0 * b10.x + mwxb1 * b11.x;
        const float r1y = mwxb0 * b10.y + mwxb1 * b11.y;
        res.z = mwy0 * r0x + mwy1 * r1x;
        res.w = mwy0 * r0y + mwy1 * r1y;
    }
    return res;
}

__global__ __launch_bounds__(NT)
void complex_scaling_kernel(const float2* __restrict__ in,
                            const float* __restrict__ theta,
                            float2* __restrict__ out)
{
    const float s = 1.0f + __ldg(theta);
    const size_t base = (size_t)blockIdx.x * (NT * BATCH) + threadIdx.x;

    if (s == 1.0f) {
        // ---- identity: 256-bit warp-batched copy (1KB per warp instr) ----
        const float* src = reinterpret_cast<const float*>(in) + base * 8;
        float* dst       = reinterpret_cast<float*>(out) + base * 8;
        const v8 v0 = ldg_v8(src + 0 * NT * 8);
        const v8 v1 = ldg_v8(src + 1 * NT * 8);
        stg_v8(dst + 0 * NT * 8, v0);
        stg_v8(dst + 1 * NT * 8, v1);
        return;
    }

    // ---- generic bilinear path: BATCH 32B chunks, 4 pixels each ----
    #pragma unroll
    for (int k = 0; k < BATCH; k++) {
        const size_t c = base + (size_t)k * NT;   // 32B chunk index
        const int p   = (int)(c * 4);             // first pixel index
        const int n   = p >> 20;                  // / (HH*WW)
        const int rem = p & (HH * WW - 1);
        const int i   = rem >> 10;                // row
        const int j0  = rem & (WW - 1);           // first column (mult of 4)

        const float yn  = (2.0f * (float)i + 1.0f) * (1.0f / (float)HH) - 1.0f;
        const float iy  = ((s * yn + 1.0f) * (float)HH - 1.0f) * 0.5f;
        const float fy0 = floorf(iy);
        const float wy1 = iy - fy0;
        const float wy0 = 1.0f - wy1;
        const int y0 = (int)fy0;
        const int y1 = y0 + 1;
        const float mwy0 = (y0 >= 0 && y0 < HH) ? wy0 : 0.0f;
        const float mwy1 = (y1 >= 0 && y1 < HH) ? wy1 : 0.0f;
        const int cy0 = min(max(y0, 0), HH - 1);
        const int cy1 = min(max(y1, 0), HH - 1);

        const float2* img = in + (size_t)n * (HH * WW);
        float4* dst = reinterpret_cast<float4*>(out) + c * 2;
        dst[0] = bilinear_pair(img, j0,     s, mwy0, mwy1, cy0, cy1);
        dst[1] = bilinear_pair(img, j0 + 2, s, mwy0, mwy1, cy0, cy1);
    }
}

extern "C" void kernel_launch(void* const* d_in, const int* in_sizes, int n_in,
                              void* d_out, int out_size)
{
    const float2* in   = (const float2*)d_in[0];   // [32,1024,1024,2] fp32
    const float* theta = (const float*)d_in[1];    // [1] fp32
    float2* out        = (float2*)d_out;

    const int blocks = NCHUNK32 / (NT * BATCH);    // 16384
    complex_scaling_kernel<<<blocks, NT>>>(in, theta, out);
}